// round 9
// baseline (speedup 1.0000x reference)
#include <cuda_runtime.h>
#include <cuda_bf16.h>

// L1 TV 1D prox (Condat 2013), batched. y (8,3,256,512) fp32, lmbd (1,3).
// lam = softplus(lmbd[c]). 6144 rows of W=512.
//
// Round 9: branchless deferred-write state machine (round-8 web, verified
// correct) + GROUP=4 lane redundancy for occupancy:
//  - 4 lanes per row run the identical select-web in lockstep (no divergence
//    cost since there are no branches) -> 768 warps instead of 192.
//  - __any_sync hoisted out of the per-trip chain (every 4 trips; done lanes
//    are no-ops in the web).
//  - forward-fill parallelized 4x across group lanes (clz last-mark + shfl
//    width-4 scan for the incoming fill value).
//  - 384 blocks x 64 threads, 16 rows/block, ~34 KB smem -> 2-3 blocks/SM.

#define TV_W 512
#define TV_STRIDE 513
#define THREADS 64
#define GROUP 4
#define ROWS_PER_BLOCK 16        // THREADS / GROUP
#define MASK_WORDS 16            // 512 bits per row
#define MASK_STRIDE 17
#define TV_C 3

__global__ void __launch_bounds__(THREADS, 1)
tv1d_condat_kernel(const float* __restrict__ y,
                   const float* __restrict__ lmbd,
                   float* __restrict__ out)
{
    extern __shared__ float s[];   // ROWS_PER_BLOCK*TV_STRIDE + masks
    float* rows = s;
    unsigned* maskbuf = (unsigned*)(s + ROWS_PER_BLOCK * TV_STRIDE);

    const int tid  = threadIdx.x;
    const int lane = tid & 31;
    const int ln   = lane & (GROUP - 1);          // lane-in-group 0..3
    const int rib  = tid >> 2;                    // row-in-block 0..15
    const size_t base = (size_t)blockIdx.x * ROWS_PER_BLOCK * TV_W;

    // ---- coalesced staged load (float4, block-cooperative) ----
    {
        const float4* g4 = (const float4*)(y + base);
        #pragma unroll 4
        for (int i = tid; i < ROWS_PER_BLOCK * (TV_W / 4); i += THREADS) {
            int r = i >> 7;            // / 128
            int q = i & 127;           // % 128
            float4 v = g4[i];
            float* d = rows + r * TV_STRIDE + (q << 2);
            d[0] = v.x; d[1] = v.y; d[2] = v.z; d[3] = v.w;
        }
    }
    // init masks (one word per thread covers 16*16=256... do strided)
    #pragma unroll
    for (int i = tid; i < ROWS_PER_BLOCK * MASK_STRIDE; i += THREADS)
        maskbuf[i] = 0u;
    __syncthreads();

    // ---- branchless Condat state machine, GROUP lanes per row ----
    float*    yr = rows    + rib * TV_STRIDE;
    unsigned* mw = maskbuf + rib * MASK_STRIDE;
    {
        const int row = blockIdx.x * ROWS_PER_BLOCK + rib;
        const int c   = (row >> 8) % TV_C;            // (row/256)%3
        const float lam  = log1pf(expf(lmbd[c]));     // softplus
        const float nlam = -lam;
        const float lam2 = 2.0f * lam;

        int   k = 0, k0 = 0, km = 0, kp = 0;
        float y0   = yr[0];
        float vmin = y0 - lam;
        float vmax = y0 + lam;
        float umin = lam;
        float umax = nlam;
        float fden = 1.0f;        // invariant: fden == (k - k0 + 1)
        bool  done = false;

        bool anyAlive = true;
        #pragma unroll 1
        for (int outer = 0; outer < 2048 && anyAlive; ++outer) {
            #pragma unroll
            for (int u = 0; u < 4; ++u) {
                // --- prefetch all shared reads ---
                float yn  = yr[min(k  + 1, TV_W - 1)];
                float rkm = yr[min(km + 1, TV_W - 1)];
                float rkp = yr[min(kp + 1, TV_W - 1)];
                int      wk0  = min(k0, TV_W - 1);
                unsigned mold = mw[wk0 >> 5];

                float fden1 = fden + 1.0f;
                float rcp1  = __fdividef(1.0f, fden1);

                float umin_t = umin + yn - vmin;
                float umax_t = umax + yn - vmax;

                // --- case flags (reference branch order) ---
                bool alive = !done;
                bool e    = (k >= TV_W - 1);
                bool neg  = (e ? (umin < 0.0f) : (umin_t < nlam)) && alive;
                bool posr =  e ? (umax > 0.0f) : (umax_t > lam);
                bool pos  = !neg && posr && alive;
                bool term = e && !neg && !pos && alive;
                bool ext  = !e && !neg && !pos && alive;
                bool jmp  = neg || pos;

                int   emit_end = neg ? km : kp;
                int   k0n      = jmp ? emit_end + 1 : k0;
                float rr       = neg ? rkm : rkp;
                float val      = neg ? vmin : vmax;

                // --- deferred segment emit ---
                yr[wk0] = val;
                mw[wk0 >> 5] = mold | (jmp ? (1u << (wk0 & 31)) : 0u);

                // --- extend-path candidates ---
                int  k1 = k + 1;
                bool hm = ext && (umin_t >= lam);
                bool hx = ext && (umax_t <= nlam);
                float vmin_ext = hm ? vmin + (umin_t - lam) * rcp1 : vmin;
                float umin_ext = hm ? lam  : umin_t;
                float vmax_ext = hx ? vmax + (umax_t + lam) * rcp1 : vmax;
                float umax_ext = hx ? nlam : umax_t;

                // --- compose new state ---
                float vmin_o = vmin, vmax_o = vmax;
                bool pe = pos && e, pb = pos && !e;
                bool ne = neg && e, nb = neg && !e;

                int   k_n    = ext ? k1 : (jmp ? k0n : k);
                int   km_n   = ext ? (hm ? k1 : km) : ((neg || pb) ? k0n : km);
                int   kp_n   = ext ? (hx ? k1 : kp) : ((pos || nb) ? k0n : kp);
                float vmin_n = ext ? vmin_ext : (neg ? rr : (pb ? rr - lam2 : vmin_o));
                float vmax_n = ext ? vmax_ext : (pos ? rr : (nb ? rr + lam2 : vmax_o));
                float umin_n = ext ? umin_ext : (pe ? rr - lam - vmin_o : (jmp ? lam  : umin));
                float umax_n = ext ? umax_ext : (ne ? rr + lam - vmax_o : (jmp ? nlam : umax));
                int   k0_n   = jmp ? k0n : k0;
                float fden_n = ext ? fden1 : (jmp ? 1.0f : fden);

                k = k_n; km = km_n; kp = kp_n; k0 = k0_n;
                vmin = vmin_n; vmax = vmax_n; umin = umin_n; umax = umax_n;
                fden = fden_n;
                done = done || term;
            }
            anyAlive = __any_sync(0xFFFFFFFFu, !done);
        }

        // --- final (terminate) segment mark ---
        {
            int wk0 = min(k0, TV_W - 1);
            yr[wk0] = vmin + umin / fden;
            mw[wk0 >> 5] |= 1u << (wk0 & 31);
        }
    }
    __syncwarp();

    // ---- forward fill, 4 lanes per row (quarter each) ----
    {
        const int ln4 = ln * 4;                    // my first mask word

        // pass A: last marked value within my quarter
        float lastv = 0.0f; int has = 0;
        #pragma unroll
        for (int w = 0; w < 4; ++w) {
            unsigned m = mw[ln4 + w];
            if (m) {
                int b = 31 - __clz(m);
                lastv = yr[((ln4 + w) << 5) + b];
                has = 1;
            }
        }

        // pass B: scan across the 4 group lanes (rightmost valid wins)
        #pragma unroll
        for (int d = 1; d < GROUP; d <<= 1) {
            float ov = __shfl_up_sync(0xFFFFFFFFu, lastv, d, GROUP);
            int   oh = __shfl_up_sync(0xFFFFFFFFu, has,  d, GROUP);
            bool take = (ln >= d) && !has;
            lastv = take ? ov : lastv;
            has   = take ? oh : has;
        }
        float inc = __shfl_up_sync(0xFFFFFFFFu, lastv, 1, GROUP);

        // pass C: fill my quarter (position 0 of the row is always marked,
        // so lane 0 never consumes its initial v)
        float v = (ln == 0) ? 0.0f : inc;
        #pragma unroll
        for (int w = 0; w < 4; ++w) {
            unsigned m = mw[ln4 + w];
            float* p = yr + ((ln4 + w) << 5);
            #pragma unroll
            for (int b = 0; b < 32; ++b) {
                float x = p[b];
                v = ((m >> b) & 1u) ? x : v;
                p[b] = v;
            }
        }
    }
    __syncthreads();

    // ---- coalesced staged store (float4, block-cooperative) ----
    {
        float4* o4 = (float4*)(out + base);
        #pragma unroll 4
        for (int i = tid; i < ROWS_PER_BLOCK * (TV_W / 4); i += THREADS) {
            int r = i >> 7;
            int q = i & 127;
            const float* d = rows + r * TV_STRIDE + (q << 2);
            o4[i] = make_float4(d[0], d[1], d[2], d[3]);
        }
    }
}

extern "C" void kernel_launch(void* const* d_in, const int* in_sizes, int n_in,
                              void* d_out, int out_size)
{
    const float* y    = (const float*)d_in[0];
    const float* lmbd = (const float*)d_in[1];
    float* out        = (float*)d_out;

    const int n_rows = in_sizes[0] / TV_W;             // 6144
    const int blocks = n_rows / ROWS_PER_BLOCK;        // 384
    const int smem   = (ROWS_PER_BLOCK * TV_STRIDE) * sizeof(float)
                     + (ROWS_PER_BLOCK * MASK_STRIDE) * sizeof(unsigned); // ~34 KB

    cudaFuncSetAttribute(tv1d_condat_kernel,
                         cudaFuncAttributeMaxDynamicSharedMemorySize, smem);

    tv1d_condat_kernel<<<blocks, THREADS, smem>>>(y, lmbd, out);
    (void)n_in; (void)out_size;
}

// round 12
// speedup vs baseline: 2.2817x; 2.2817x over previous
#include <cuda_runtime.h>
#include <cuda_bf16.h>

// L1 TV 1D prox (Condat 2013), batched. y (8,3,256,512) fp32, lmbd (1,3).
// lam = softplus(lmbd[c]). 6144 rows of W=512, ONE THREAD PER ROW (GROUP=1).
//
// Round 10: phase-split branchless state machine with deferred writes.
//  Phase 1 (bulk): slim web, no boundary/done logic, no index clamps
//    (k0 <= k < 511 => indices statically safe; row pad absorbs k+1=512).
//    Frozen lanes (k==511) are no-ops via a single 'act' guard.
//  Phase 2 (tail): full round-8 web incl. boundary flush/terminate.
//  Deferred segment emits: value at segment start + bit mask; forward-fill
//  pass reconstructs the row afterwards.
//  192 blocks x 32 threads -> all 148 SMs populated.

#define TV_W 512
#define TV_STRIDE 513            // +1 pad
#define THREADS 32
#define MASK_WORDS 16            // 512 bits per row
#define MASK_STRIDE 17
#define TV_C 3

__global__ void __launch_bounds__(THREADS, 1)
tv1d_condat_kernel(const float* __restrict__ y,
                   const float* __restrict__ lmbd,
                   float* __restrict__ out)
{
    extern __shared__ float s[];   // THREADS*TV_STRIDE + THREADS*MASK_STRIDE
    float* rows = s;
    unsigned* maskbuf = (unsigned*)(s + THREADS * TV_STRIDE);

    const int tid = threadIdx.x;
    const size_t base = (size_t)blockIdx.x * THREADS * TV_W;

    // ---- coalesced staged load (float4) ----
    {
        const float4* g4 = (const float4*)(y + base);
        #pragma unroll 4
        for (int i = tid; i < THREADS * (TV_W / 4); i += THREADS) {
            int r = i >> 7;            // / 128
            int q = i & 127;           // % 128
            float4 v = g4[i];
            float* d = rows + r * TV_STRIDE + (q << 2);
            d[0] = v.x; d[1] = v.y; d[2] = v.z; d[3] = v.w;
        }
    }
    unsigned* mw = maskbuf + tid * MASK_STRIDE;
    #pragma unroll
    for (int w = 0; w < MASK_WORDS; ++w) mw[w] = 0u;
    __syncwarp();

    // ---- branchless Condat state machine ----
    float* yr = rows + tid * TV_STRIDE;
    {
        const int row = blockIdx.x * THREADS + tid;
        const int c   = (row >> 8) % TV_C;            // (row/256)%3
        const float lam  = log1pf(expf(lmbd[c]));     // softplus
        const float nlam = -lam;
        const float lam2 = 2.0f * lam;

        int   k = 0, k0 = 0, km = 0, kp = 0;
        float y0   = yr[0];
        float vmin = y0 - lam;
        float vmax = y0 + lam;
        float umin = lam;
        float umax = nlam;
        float fden = 1.0f;        // invariant: fden == (k - k0 + 1)

        // ======== PHASE 1: k < W-1 only (no boundary/done logic) ========
        #pragma unroll 1
        for (int it = 0; it < 1024; ++it) {
            if (!__any_sync(0xFFFFFFFFu, k < TV_W - 1)) break;
            #pragma unroll
            for (int u = 0; u < 4; ++u) {
                // indices: k0 <= km,kp <= k <= 511 -> all reads in [1,512] safe
                float yn  = yr[k  + 1];
                float rkm = yr[km + 1];
                float rkp = yr[kp + 1];
                unsigned mold = mw[k0 >> 5];

                float fden1 = fden + 1.0f;
                float rcp1  = __fdividef(1.0f, fden1);
                float umin_t = umin + yn - vmin;
                float umax_t = umax + yn - vmax;

                bool act = k < TV_W - 1;
                bool neg = act && (umin_t < nlam);
                bool pos = act && !neg && (umax_t > lam);
                bool jmp = neg || pos;
                bool ext = act && !jmp;

                int   emit_end = neg ? km : kp;
                int   k0n      = emit_end + 1;
                float rr       = neg ? rkm : rkp;
                float val      = neg ? vmin : vmax;

                // deferred emit (yr[k0] is never read again; its bit is unset)
                yr[k0] = val;
                mw[k0 >> 5] = mold | (jmp ? (1u << (k0 & 31)) : 0u);

                int  k1 = k + 1;
                bool hm = ext && (umin_t >= lam);
                bool hx = ext && (umax_t <= nlam);
                float vmin_ext = hm ? vmin + (umin_t - lam) * rcp1 : vmin;
                float umin_ext = hm ? lam  : umin_t;
                float vmax_ext = hx ? vmax + (umax_t + lam) * rcp1 : vmax;
                float umax_ext = hx ? nlam : umax_t;

                k    = ext ? k1 : (jmp ? k0n : k);
                km   = ext ? (hm ? k1 : km) : (jmp ? k0n : km);
                kp   = ext ? (hx ? k1 : kp) : (jmp ? k0n : kp);
                vmin = ext ? vmin_ext : (jmp ? (neg ? rr : rr - lam2) : vmin);
                vmax = ext ? vmax_ext : (jmp ? (neg ? rr + lam2 : rr) : vmax);
                umin = ext ? umin_ext : (jmp ? lam  : umin);
                umax = ext ? umax_ext : (jmp ? nlam : umax);
                k0   = jmp ? k0n : k0;
                fden = ext ? fden1 : (jmp ? 1.0f : fden);
            }
        }

        // ======== PHASE 2: full web (boundary + terminate), short tail ====
        bool done = false;
        #pragma unroll 1
        for (int it = 0; it < 4096; ++it) {
            if (!__any_sync(0xFFFFFFFFu, !done)) break;

            float yn  = yr[min(k  + 1, TV_W - 1)];
            float rkm = yr[min(km + 1, TV_W - 1)];
            float rkp = yr[min(kp + 1, TV_W - 1)];
            int      wk0  = min(k0, TV_W - 1);
            unsigned mold = mw[wk0 >> 5];

            float fden1 = fden + 1.0f;
            float rcp1  = __fdividef(1.0f, fden1);
            float umin_t = umin + yn - vmin;
            float umax_t = umax + yn - vmax;

            bool alive = !done;
            bool e    = (k >= TV_W - 1);
            bool neg  = (e ? (umin < 0.0f) : (umin_t < nlam)) && alive;
            bool posr =  e ? (umax > 0.0f) : (umax_t > lam);
            bool pos  = !neg && posr && alive;
            bool term = e && !neg && !pos && alive;
            bool ext  = !e && !neg && !pos && alive;
            bool jmp  = neg || pos;

            int   emit_end = neg ? km : kp;
            int   k0n      = jmp ? emit_end + 1 : k0;
            float rr       = neg ? rkm : rkp;
            float val      = neg ? vmin : vmax;

            yr[wk0] = val;
            mw[wk0 >> 5] = mold | (jmp ? (1u << (wk0 & 31)) : 0u);

            int  k1 = k + 1;
            bool hm = ext && (umin_t >= lam);
            bool hx = ext && (umax_t <= nlam);
            float vmin_ext = hm ? vmin + (umin_t - lam) * rcp1 : vmin;
            float umin_ext = hm ? lam  : umin_t;
            float vmax_ext = hx ? vmax + (umax_t + lam) * rcp1 : vmax;
            float umax_ext = hx ? nlam : umax_t;

            float vmin_o = vmin, vmax_o = vmax;
            bool pe = pos && e, pb = pos && !e;
            bool ne = neg && e, nb = neg && !e;

            int   k_n    = ext ? k1 : (jmp ? k0n : k);
            int   km_n   = ext ? (hm ? k1 : km) : ((neg || pb) ? k0n : km);
            int   kp_n   = ext ? (hx ? k1 : kp) : ((pos || nb) ? k0n : kp);
            float vmin_n = ext ? vmin_ext : (neg ? rr : (pb ? rr - lam2 : vmin_o));
            float vmax_n = ext ? vmax_ext : (pos ? rr : (nb ? rr + lam2 : vmax_o));
            float umin_n = ext ? umin_ext : (pe ? rr - lam - vmin_o : (jmp ? lam  : umin));
            float umax_n = ext ? umax_ext : (ne ? rr + lam - vmax_o : (jmp ? nlam : umax));
            int   k0_n   = jmp ? k0n : k0;
            float fden_n = ext ? fden1 : (jmp ? 1.0f : fden);

            k = k_n; km = km_n; kp = kp_n; k0 = k0_n;
            vmin = vmin_n; vmax = vmax_n; umin = umin_n; umax = umax_n;
            fden = fden_n;
            done = done || term;
        }

        // --- final (terminate) segment mark ---
        {
            int wk0 = min(k0, TV_W - 1);
            yr[wk0] = vmin + umin / fden;
            mw[wk0 >> 5] |= 1u << (wk0 & 31);
        }

        // --- forward-fill: expand (start,value) marks to full row ---
        {
            float v = 0.0f;
            #pragma unroll 1
            for (int w = 0; w < MASK_WORDS; ++w) {
                unsigned m = mw[w];
                float* p = yr + (w << 5);
                #pragma unroll
                for (int b = 0; b < 32; ++b) {
                    float x = p[b];
                    v = ((m >> b) & 1u) ? x : v;
                    p[b] = v;
                }
            }
        }
    }
    __syncwarp();

    // ---- coalesced staged store (float4) ----
    {
        float4* o4 = (float4*)(out + base);
        #pragma unroll 4
        for (int i = tid; i < THREADS * (TV_W / 4); i += THREADS) {
            int r = i >> 7;
            int q = i & 127;
            const float* d = rows + r * TV_STRIDE + (q << 2);
            o4[i] = make_float4(d[0], d[1], d[2], d[3]);
        }
    }
}

extern "C" void kernel_launch(void* const* d_in, const int* in_sizes, int n_in,
                              void* d_out, int out_size)
{
    const float* y    = (const float*)d_in[0];
    const float* lmbd = (const float*)d_in[1];
    float* out        = (float*)d_out;

    const int n_rows = in_sizes[0] / TV_W;       // 6144
    const int blocks = n_rows / THREADS;         // 192
    const int smem   = (THREADS * TV_STRIDE) * sizeof(float)
                     + (THREADS * MASK_STRIDE) * sizeof(unsigned);  // 67840 B

    cudaFuncSetAttribute(tv1d_condat_kernel,
                         cudaFuncAttributeMaxDynamicSharedMemorySize, smem);

    tv1d_condat_kernel<<<blocks, THREADS, smem>>>(y, lmbd, out);
    (void)n_in; (void)out_size;
}